// round 2
// baseline (speedup 1.0000x reference)
#include <cuda_runtime.h>

#define Nn 10000
#define Ee 160000
#define Cc 8
#define Bb 64
#define EPSv 1e-5f

// Scratch (device globals; allocation-free per harness rules)
__device__ float g_xT[Ee * Bb];        // x transposed (E,B)
__device__ float g_h[Nn * Bb * Cc];    // LN+ELU activations, layout (N, B, C)
__device__ int   g_cnt[Nn];
__device__ int   g_cursor[Nn];
__device__ int   g_start[Nn + 1];
__device__ int   g_sorted[Ee];

// ---------------- CSR build (counting sort by edge_dst) ----------------

__global__ void zero_counts_kernel() {
    int i = blockIdx.x * blockDim.x + threadIdx.x;
    if (i < Nn) g_cnt[i] = 0;
}

__global__ void hist_kernel(const int* __restrict__ dst) {
    int e = blockIdx.x * blockDim.x + threadIdx.x;
    if (e < Ee) atomicAdd(&g_cnt[dst[e]], 1);
}

// Single-block exclusive scan over N=10000 counts; also seeds g_cursor = g_start
__global__ void scan_kernel() {
    __shared__ int sh[1024];
    const int CH = (Nn + 1023) / 1024;  // 10
    int t = threadIdx.x;
    int base = t * CH;
    int loc[CH];
    int s = 0;
#pragma unroll
    for (int i = 0; i < CH; i++) {
        int v = (base + i < Nn) ? g_cnt[base + i] : 0;
        loc[i] = s;
        s += v;
    }
    sh[t] = s;
    __syncthreads();
    for (int off = 1; off < 1024; off <<= 1) {
        int v = (t >= off) ? sh[t - off] : 0;
        __syncthreads();
        if (t >= off) sh[t] += v;
        __syncthreads();
    }
    int prev = (t > 0) ? sh[t - 1] : 0;
#pragma unroll
    for (int i = 0; i < CH; i++)
        if (base + i < Nn) {
            int v = prev + loc[i];
            g_start[base + i] = v;
            g_cursor[base + i] = v;
        }
    if (t == 1023) g_start[Nn] = sh[1023];
}

// 4 edges per thread: 4 concurrent ATOMGs hide the ~318cyc latency
__global__ void sort_scatter_kernel(const int* __restrict__ dst) {
    int base = (blockIdx.x * blockDim.x + threadIdx.x) * 4;
#pragma unroll
    for (int k = 0; k < 4; k++) {
        int e = base + k;
        if (e < Ee) {
            int d = dst[e];
            int p = atomicAdd(&g_cursor[d], 1);
            g_sorted[p] = e;
        }
    }
}

// ---------------- Transpose x (B,E) -> xT (E,B) ----------------

__global__ void transpose_x_kernel(const float* __restrict__ x) {
    __shared__ float tile[32][33];
    int e0 = blockIdx.x * 32;
    int b0 = blockIdx.y * 32;
    int tx = threadIdx.x, ty = threadIdx.y;  // block (32,8)
#pragma unroll
    for (int i = 0; i < 32; i += 8)
        tile[ty + i][tx] = x[(b0 + ty + i) * Ee + e0 + tx];
    __syncthreads();
#pragma unroll
    for (int i = 0; i < 32; i += 8)
        g_xT[(e0 + ty + i) * Bb + b0 + tx] = tile[tx][ty + i];
}

// ---------------- Fused scatter + bias + LayerNorm + ELU ----------------
// 64 threads per node (one per batch b); C=8 accumulators in registers.

__global__ void scatter_ln_kernel(const float* __restrict__ w1,
                                  const float* __restrict__ b1,
                                  const float* __restrict__ gamma,
                                  const float* __restrict__ beta) {
    int node = blockIdx.x * 4 + (threadIdx.x >> 6);
    int b    = threadIdx.x & 63;
    if (node >= Nn) return;

    float acc[8];
#pragma unroll
    for (int j = 0; j < 8; j++) acc[j] = 0.0f;

    int s  = g_start[node];
    int se = g_start[node + 1];

    // software-pipelined edge loop: prefetch next edge id
    int e = (s < se) ? g_sorted[s] : 0;
    for (int i = s; i < se; i++) {
        int en = (i + 1 < se) ? g_sorted[i + 1] : 0;
        float xv = g_xT[e * Bb + b];              // coalesced 256B per 64-group
        float4 wa = *reinterpret_cast<const float4*>(w1 + e * 8);
        float4 wb = *reinterpret_cast<const float4*>(w1 + e * 8 + 4);
        acc[0] = fmaf(xv, wa.x, acc[0]);
        acc[1] = fmaf(xv, wa.y, acc[1]);
        acc[2] = fmaf(xv, wa.z, acc[2]);
        acc[3] = fmaf(xv, wa.w, acc[3]);
        acc[4] = fmaf(xv, wb.x, acc[4]);
        acc[5] = fmaf(xv, wb.y, acc[5]);
        acc[6] = fmaf(xv, wb.z, acc[6]);
        acc[7] = fmaf(xv, wb.w, acc[7]);
        e = en;
    }

    float4 c0 = *reinterpret_cast<const float4*>(b1 + node * 8);
    float4 c1 = *reinterpret_cast<const float4*>(b1 + node * 8 + 4);
    acc[0] += c0.x; acc[1] += c0.y; acc[2] += c0.z; acc[3] += c0.w;
    acc[4] += c1.x; acc[5] += c1.y; acc[6] += c1.z; acc[7] += c1.w;

    float mu = 0.0f;
#pragma unroll
    for (int j = 0; j < 8; j++) mu += acc[j];
    mu *= 0.125f;
    float var = 0.0f;
#pragma unroll
    for (int j = 0; j < 8; j++) { float d = acc[j] - mu; var = fmaf(d, d, var); }
    var *= 0.125f;
    float r = rsqrtf(var + EPSv);

    float4 ga = *reinterpret_cast<const float4*>(gamma + node * 8);
    float4 gb = *reinterpret_cast<const float4*>(gamma + node * 8 + 4);
    float4 ba = *reinterpret_cast<const float4*>(beta  + node * 8);
    float4 bb = *reinterpret_cast<const float4*>(beta  + node * 8 + 4);

    float gv[8] = {ga.x, ga.y, ga.z, ga.w, gb.x, gb.y, gb.z, gb.w};
    float bv[8] = {ba.x, ba.y, ba.z, ba.w, bb.x, bb.y, bb.z, bb.w};

    float h[8];
#pragma unroll
    for (int j = 0; j < 8; j++) {
        float v = fmaf((acc[j] - mu) * r, gv[j], bv[j]);
        h[j] = (v > 0.0f) ? v : expm1f(v);        // ELU, alpha=1
    }

    float* hp = g_h + node * (Bb * Cc) + b * Cc;
    *reinterpret_cast<float4*>(hp)     = make_float4(h[0], h[1], h[2], h[3]);
    *reinterpret_cast<float4*>(hp + 4) = make_float4(h[4], h[5], h[6], h[7]);
}

// ---------------- Fused gather + residual, direct (B,E) output ----------------
// One thread per edge; loop over b. Writes out[b*E+e] coalesced; h reads hit L2.

__global__ void gather_out_kernel(const float* __restrict__ w3,
                                  const float* __restrict__ b3,
                                  const int* __restrict__ src,
                                  const float* __restrict__ x,
                                  float* __restrict__ out) {
    int e = blockIdx.x * blockDim.x + threadIdx.x;
    if (e >= Ee) return;
    int sn = src[e];
    float4 wa = *reinterpret_cast<const float4*>(w3 + e * 8);
    float4 wb = *reinterpret_cast<const float4*>(w3 + e * 8 + 4);
    float bias = b3[e];
    const float* hp = g_h + sn * (Bb * Cc);

#pragma unroll 4
    for (int b = 0; b < Bb; b++) {
        float4 ha = *reinterpret_cast<const float4*>(hp + b * 8);
        float4 hb = *reinterpret_cast<const float4*>(hp + b * 8 + 4);
        float sum = bias;
        sum = fmaf(ha.x, wa.x, sum);
        sum = fmaf(ha.y, wa.y, sum);
        sum = fmaf(ha.z, wa.z, sum);
        sum = fmaf(ha.w, wa.w, sum);
        sum = fmaf(hb.x, wb.x, sum);
        sum = fmaf(hb.y, wb.y, sum);
        sum = fmaf(hb.z, wb.z, sum);
        sum = fmaf(hb.w, wb.w, sum);
        out[b * Ee + e] = sum + x[b * Ee + e];
    }
}

// ---------------- Launch ----------------

extern "C" void kernel_launch(void* const* d_in, const int* in_sizes, int n_in,
                              void* d_out, int out_size) {
    const float* x     = (const float*)d_in[0];   // (B,E)
    const float* w1    = (const float*)d_in[1];   // (E,C)
    const float* b1    = (const float*)d_in[2];   // (N,C)
    const float* gamma = (const float*)d_in[3];   // (N,C)
    const float* beta  = (const float*)d_in[4];   // (N,C)
    const float* w3    = (const float*)d_in[5];   // (E,C)
    const float* b3    = (const float*)d_in[6];   // (E,)
    const int* edge_src = (const int*)d_in[7];    // (E,)
    const int* edge_dst = (const int*)d_in[8];    // (E,)
    float* out = (float*)d_out;                   // (B,E)

    // CSR build
    zero_counts_kernel<<<(Nn + 255) / 256, 256>>>();
    hist_kernel<<<(Ee + 255) / 256, 256>>>(edge_dst);
    scan_kernel<<<1, 1024>>>();
    sort_scatter_kernel<<<(Ee / 4 + 255) / 256, 256>>>(edge_dst);

    // Transpose x
    transpose_x_kernel<<<dim3(Ee / 32, Bb / 32), dim3(32, 8)>>>(x);

    // Fused scatter + LN + ELU
    scatter_ln_kernel<<<(Nn + 3) / 4, 256>>>(w1, b1, gamma, beta);

    // Fused gather + residual, writes (B,E) directly
    gather_out_kernel<<<(Ee + 127) / 128, 128>>>(w3, b3, edge_src, x, out);
}

// round 3
// speedup vs baseline: 1.3310x; 1.3310x over previous
#include <cuda_runtime.h>

#define Nn 10000
#define Ee 160000
#define Cc 8
#define Bb 64
#define EPSv 1e-5f

// Scratch (device globals; allocation-free per harness rules)
__device__ float g_xT[Ee * Bb];        // x transposed (E,B)
__device__ float g_h[Nn * Bb * Cc];    // LN+ELU activations, layout (N, B, C)
__device__ int   g_cnt[Nn];
__device__ int   g_cursor[Nn];
__device__ int   g_start[Nn + 1];
__device__ int   g_sorted[Ee];

// ---------------- hist + transpose fused (role-split grid) ----------------
// Blocks [0, HIST_BLOCKS): histogram of edge_dst (atomic-latency-bound).
// Blocks [HIST_BLOCKS, ...): tiled transpose x (B,E) -> xT (E,B) (DRAM-bound).
// Independent work on complementary pipes -> overlap.

#define HIST_BLOCKS 625           // 625*256 = 160000
#define TR_BLOCKS_X 5000          // Ee/32
#define TR_BLOCKS_Y 2             // Bb/32

__global__ void hist_transpose_kernel(const int* __restrict__ dst,
                                      const float* __restrict__ x) {
    int bid = blockIdx.x;
    if (bid < HIST_BLOCKS) {
        int e = bid * 256 + threadIdx.x;
        if (e < Ee) atomicAdd(&g_cnt[dst[e]], 1);
        return;
    }
    int tb = bid - HIST_BLOCKS;
    int e0 = (tb % TR_BLOCKS_X) * 32;
    int b0 = (tb / TR_BLOCKS_X) * 32;
    int tx = threadIdx.x & 31;
    int ty = threadIdx.x >> 5;    // 0..7
    __shared__ float tile[32][33];
#pragma unroll
    for (int i = 0; i < 32; i += 8)
        tile[ty + i][tx] = x[(b0 + ty + i) * Ee + e0 + tx];
    __syncthreads();
#pragma unroll
    for (int i = 0; i < 32; i += 8)
        g_xT[(e0 + ty + i) * Bb + b0 + tx] = tile[tx][ty + i];
}

// Single-block exclusive scan over N=10000 counts; also seeds g_cursor = g_start
__global__ void scan_kernel() {
    __shared__ int sh[1024];
    const int CH = (Nn + 1023) / 1024;  // 10
    int t = threadIdx.x;
    int base = t * CH;
    int loc[CH];
    int s = 0;
#pragma unroll
    for (int i = 0; i < CH; i++) {
        int v = (base + i < Nn) ? g_cnt[base + i] : 0;
        loc[i] = s;
        s += v;
    }
    sh[t] = s;
    __syncthreads();
    for (int off = 1; off < 1024; off <<= 1) {
        int v = (t >= off) ? sh[t - off] : 0;
        __syncthreads();
        if (t >= off) sh[t] += v;
        __syncthreads();
    }
    int prev = (t > 0) ? sh[t - 1] : 0;
#pragma unroll
    for (int i = 0; i < CH; i++)
        if (base + i < Nn) {
            int v = prev + loc[i];
            g_start[base + i] = v;
            g_cursor[base + i] = v;
        }
    if (t == 1023) g_start[Nn] = sh[1023];
}

// 1 edge per thread (R1 config: best measured) — wide grid hides ATOMG latency
__global__ void sort_scatter_kernel(const int* __restrict__ dst) {
    int e = blockIdx.x * blockDim.x + threadIdx.x;
    if (e < Ee) {
        int d = dst[e];
        int p = atomicAdd(&g_cursor[d], 1);
        g_sorted[p] = e;
    }
}

// ---------------- Fused scatter + bias + LayerNorm + ELU ----------------
// 64 threads per node (one per batch b); C=8 accumulators in registers.

__global__ void scatter_ln_kernel(const float* __restrict__ w1,
                                  const float* __restrict__ b1,
                                  const float* __restrict__ gamma,
                                  const float* __restrict__ beta) {
    int node = blockIdx.x * 4 + (threadIdx.x >> 6);
    int b    = threadIdx.x & 63;
    if (node >= Nn) return;

    float acc[8];
#pragma unroll
    for (int j = 0; j < 8; j++) acc[j] = 0.0f;

    int s  = g_start[node];
    int se = g_start[node + 1];

    // software-pipelined edge loop: prefetch next edge id
    int e = (s < se) ? g_sorted[s] : 0;
    for (int i = s; i < se; i++) {
        int en = (i + 1 < se) ? g_sorted[i + 1] : 0;
        float xv = g_xT[e * Bb + b];              // coalesced 256B per 64-group
        float4 wa = *reinterpret_cast<const float4*>(w1 + e * 8);
        float4 wb = *reinterpret_cast<const float4*>(w1 + e * 8 + 4);
        acc[0] = fmaf(xv, wa.x, acc[0]);
        acc[1] = fmaf(xv, wa.y, acc[1]);
        acc[2] = fmaf(xv, wa.z, acc[2]);
        acc[3] = fmaf(xv, wa.w, acc[3]);
        acc[4] = fmaf(xv, wb.x, acc[4]);
        acc[5] = fmaf(xv, wb.y, acc[5]);
        acc[6] = fmaf(xv, wb.z, acc[6]);
        acc[7] = fmaf(xv, wb.w, acc[7]);
        e = en;
    }

    float4 c0 = *reinterpret_cast<const float4*>(b1 + node * 8);
    float4 c1 = *reinterpret_cast<const float4*>(b1 + node * 8 + 4);
    acc[0] += c0.x; acc[1] += c0.y; acc[2] += c0.z; acc[3] += c0.w;
    acc[4] += c1.x; acc[5] += c1.y; acc[6] += c1.z; acc[7] += c1.w;

    float mu = 0.0f;
#pragma unroll
    for (int j = 0; j < 8; j++) mu += acc[j];
    mu *= 0.125f;
    float var = 0.0f;
#pragma unroll
    for (int j = 0; j < 8; j++) { float d = acc[j] - mu; var = fmaf(d, d, var); }
    var *= 0.125f;
    float r = rsqrtf(var + EPSv);

    float4 ga = *reinterpret_cast<const float4*>(gamma + node * 8);
    float4 gb = *reinterpret_cast<const float4*>(gamma + node * 8 + 4);
    float4 ba = *reinterpret_cast<const float4*>(beta  + node * 8);
    float4 bb = *reinterpret_cast<const float4*>(beta  + node * 8 + 4);

    float gv[8] = {ga.x, ga.y, ga.z, ga.w, gb.x, gb.y, gb.z, gb.w};
    float bv[8] = {ba.x, ba.y, ba.z, ba.w, bb.x, bb.y, bb.z, bb.w};

    float h[8];
#pragma unroll
    for (int j = 0; j < 8; j++) {
        float v = fmaf((acc[j] - mu) * r, gv[j], bv[j]);
        h[j] = (v > 0.0f) ? v : expm1f(v);        // ELU, alpha=1
    }

    float* hp = g_h + node * (Bb * Cc) + b * Cc;
    *reinterpret_cast<float4*>(hp)     = make_float4(h[0], h[1], h[2], h[3]);
    *reinterpret_cast<float4*>(hp + 4) = make_float4(h[4], h[5], h[6], h[7]);
}

// ---------------- Fused gather + transpose + residual via smem staging ----------------
// Block = 64 edges x 64 b. Phase 1: b in lanes (coalesced 2KB h-tile reads),
// results to smem. Phase 2: transposed coalesced write out[b*E+e] + x residual.

#define GE 64  // edges per block

__global__ void gather_fused_kernel(const float* __restrict__ w3,
                                    const float* __restrict__ b3,
                                    const int* __restrict__ src,
                                    const float* __restrict__ x,
                                    float* __restrict__ out) {
    __shared__ float tile[Bb][GE + 1];
    int e0 = blockIdx.x * GE;
    int t = threadIdx.x;          // 256
    int b = t & 63;
    int g = t >> 6;               // 0..3

    // Phase 1: each 64-thread group handles edges i = g, g+4, ... (16 each)
#pragma unroll 4
    for (int i = g; i < GE; i += 4) {
        int e = e0 + i;
        int sn = __ldg(src + e);                   // uniform within group
        const float* hp = g_h + sn * (Bb * Cc) + b * Cc;
        float4 ha = *reinterpret_cast<const float4*>(hp);
        float4 hb = *reinterpret_cast<const float4*>(hp + 4);
        float4 wa = *reinterpret_cast<const float4*>(w3 + e * 8);
        float4 wb = *reinterpret_cast<const float4*>(w3 + e * 8 + 4);
        float sum = __ldg(b3 + e);
        sum = fmaf(ha.x, wa.x, sum);
        sum = fmaf(ha.y, wa.y, sum);
        sum = fmaf(ha.z, wa.z, sum);
        sum = fmaf(ha.w, wa.w, sum);
        sum = fmaf(hb.x, wb.x, sum);
        sum = fmaf(hb.y, wb.y, sum);
        sum = fmaf(hb.z, wb.z, sum);
        sum = fmaf(hb.w, wb.w, sum);
        tile[b][i] = sum;                          // stride-65: conflict-free
    }
    __syncthreads();

    // Phase 2: coalesced transposed write with residual
    int el = t & 63;
#pragma unroll
    for (int k = 0; k < 16; k++) {
        int b2 = (t >> 6) + k * 4;
        int idx = b2 * Ee + e0 + el;
        out[idx] = tile[b2][el] + x[idx];
    }
}

// ---------------- Launch ----------------

extern "C" void kernel_launch(void* const* d_in, const int* in_sizes, int n_in,
                              void* d_out, int out_size) {
    const float* x     = (const float*)d_in[0];   // (B,E)
    const float* w1    = (const float*)d_in[1];   // (E,C)
    const float* b1    = (const float*)d_in[2];   // (N,C)
    const float* gamma = (const float*)d_in[3];   // (N,C)
    const float* beta  = (const float*)d_in[4];   // (N,C)
    const float* w3    = (const float*)d_in[5];   // (E,C)
    const float* b3    = (const float*)d_in[6];   // (E,)
    const int* edge_src = (const int*)d_in[7];    // (E,)
    const int* edge_dst = (const int*)d_in[8];    // (E,)
    float* out = (float*)d_out;                   // (B,E)

    // Zero histogram (memset node instead of kernel)
    void* cnt_ptr = nullptr;
    cudaGetSymbolAddress(&cnt_ptr, g_cnt);
    cudaMemsetAsync(cnt_ptr, 0, Nn * sizeof(int));

    // hist (atomics) overlapped with transpose (DRAM)
    hist_transpose_kernel<<<HIST_BLOCKS + TR_BLOCKS_X * TR_BLOCKS_Y, 256>>>(edge_dst, x);

    // scan (also seeds cursor), then stable-ish counting-sort scatter
    scan_kernel<<<1, 1024>>>();
    sort_scatter_kernel<<<(Ee + 255) / 256, 256>>>(edge_dst);

    // Fused scatter + LN + ELU
    scatter_ln_kernel<<<(Nn + 3) / 4, 256>>>(w1, b1, gamma, beta);

    // Fused gather + transpose + residual
    gather_fused_kernel<<<Ee / GE, 256>>>(w3, b3, edge_src, x, out);
}